// round 1
// baseline (speedup 1.0000x reference)
#include <cuda_runtime.h>
#include <math.h>

#define EPSV 1e-5f
constexpr int CIN = 48;

// ---------------- scratch buffers (no allocation allowed) ----------------
__device__ float g_a[4*48*64*64];
__device__ float g_b[4*48*64*64];
__device__ float g_c[4*48*32*32];
__device__ float g_d[4*48*32*32];
__device__ float g_sk[4*9*32*32];

// ---------------- x1 = x_[:, :, ::4, ::4] ----------------
__global__ void down_kernel(const float* __restrict__ xs, float* __restrict__ out) {
    int i = blockIdx.x * blockDim.x + threadIdx.x;
    if (i >= 4*48*64*64) return;
    int w  = i & 63;
    int t  = i >> 6;
    int h  = t & 63;
    int nc = t >> 6;
    out[i] = xs[((size_t)nc * 256 + (size_t)h * 4) * 256 + (size_t)w * 4];
}

// ---------------- 2x2 maxpool: (4,48,64,64) -> (4,48,32,32) ----------------
__global__ void pool_kernel(const float* __restrict__ in, float* __restrict__ out) {
    int i = blockIdx.x * blockDim.x + threadIdx.x;
    if (i >= 4*48*32*32) return;
    int w  = i & 31;
    int t  = i >> 5;
    int h  = t & 31;
    int nc = t >> 5;
    const float* p = in + ((size_t)nc * 64 + (size_t)h * 2) * 64 + (size_t)w * 2;
    out[i] = fmaxf(fmaxf(p[0], p[1]), fmaxf(p[64], p[65]));
}

// ---------------- block-wide (sum, sumsq) reduction over 256 threads ----------------
__device__ __forceinline__ void blk_stats(float lsum, float lsq, float* sred, int tid,
                                          float inv, float& mean, float& var) {
    __syncthreads();   // protect sred reuse across successive calls
    #pragma unroll
    for (int o = 16; o; o >>= 1) {
        lsum += __shfl_xor_sync(0xffffffffu, lsum, o);
        lsq  += __shfl_xor_sync(0xffffffffu, lsq,  o);
    }
    if ((tid & 31) == 0) { sred[tid >> 5] = lsum; sred[8 + (tid >> 5)] = lsq; }
    __syncthreads();
    if (tid == 0) {
        float a = 0.f, b = 0.f;
        #pragma unroll
        for (int i = 0; i < 8; i++) { a += sred[i]; b += sred[8 + i]; }
        sred[16] = a; sred[17] = b;
    }
    __syncthreads();
    mean = sred[16] * inv;
    var  = sred[17] * inv - mean * mean;
}

// ---------------- fused conv3x3(48->COUT) + optional inorm/prelu/inorm/residual ----------
// MODE 0: conv+bias, inorm, prelu, inorm, +residual   (basic block)
// MODE 1: conv+bias, inorm, prelu                     (prek stage 1)
// MODE 2: conv+bias                                   (skernel conv, COUT=9)
// Grid: (COUT, N). Block: 256 threads as 16x16, each thread owns TP x TP pixels.
template <int H, int TP, int MODE>
__global__ void __launch_bounds__(256)
conv_block(const float* __restrict__ in, const float* __restrict__ resid,
           float* __restrict__ out,
           const float* __restrict__ W, const float* __restrict__ B,
           const float* __restrict__ alpha_ptr) {
    constexpr int S = H + 3;                 // padded smem row stride (odd)
    __shared__ float s_in[(H + 2) * S];
    __shared__ float s_w[CIN * 9];
    __shared__ float s_red[18];

    const int cout = blockIdx.x;
    const int n    = blockIdx.y;
    const int tid  = threadIdx.x;
    const int tx   = tid & 15;
    const int ty   = tid >> 4;
    const int px0  = tx * TP;
    const int py0  = ty * TP;

    // cache this cout's weight slice (CIN*9 contiguous)
    const float* wsrc = W + (size_t)cout * CIN * 9;
    for (int i = tid; i < CIN * 9; i += 256) s_w[i] = wsrc[i];

    float acc[TP][TP];
    #pragma unroll
    for (int r = 0; r < TP; r++)
        #pragma unroll
        for (int c = 0; c < TP; c++) acc[r][c] = 0.f;

    const float* inb = in + (size_t)n * CIN * H * H;

    for (int ci = 0; ci < CIN; ++ci) {
        __syncthreads();
        const float* ch = inb + (size_t)ci * H * H;
        // cooperative load of padded channel tile (zero SAME padding)
        for (int e = tid; e < (H + 2) * (H + 2); e += 256) {
            int r = e / (H + 2), c = e - r * (H + 2);
            int gr = r - 1, gc = c - 1;
            float v = 0.f;
            if ((unsigned)gr < (unsigned)H && (unsigned)gc < (unsigned)H)
                v = ch[gr * H + gc];
            s_in[r * S + c] = v;
        }
        __syncthreads();

        float w[9];
        #pragma unroll
        for (int k = 0; k < 9; k++) w[k] = s_w[ci * 9 + k];

        float win[TP + 2][TP + 2];
        #pragma unroll
        for (int r = 0; r < TP + 2; r++)
            #pragma unroll
            for (int c = 0; c < TP + 2; c++)
                win[r][c] = s_in[(py0 + r) * S + (px0 + c)];

        #pragma unroll
        for (int r = 0; r < TP; r++)
            #pragma unroll
            for (int c = 0; c < TP; c++)
                #pragma unroll
                for (int dy = 0; dy < 3; dy++)
                    #pragma unroll
                    for (int dx = 0; dx < 3; dx++)
                        acc[r][c] = fmaf(win[r + dy][c + dx], w[dy * 3 + dx], acc[r][c]);
    }

    const float bias = B[cout];
    const int COUT = gridDim.x;
    float* ob = out + ((size_t)n * COUT + cout) * H * H;

    if (MODE == 2) {
        #pragma unroll
        for (int r = 0; r < TP; r++)
            #pragma unroll
            for (int c = 0; c < TP; c++)
                ob[(py0 + r) * H + (px0 + c)] = acc[r][c] + bias;
        return;
    }

    const float inv = 1.0f / (float)(H * H);
    float lsum = 0.f, lsq = 0.f;
    #pragma unroll
    for (int r = 0; r < TP; r++)
        #pragma unroll
        for (int c = 0; c < TP; c++) {
            acc[r][c] += bias;
            lsum += acc[r][c];
            lsq  += acc[r][c] * acc[r][c];
        }
    float m, v;
    blk_stats(lsum, lsq, s_red, tid, inv, m, v);
    float rs = rsqrtf(v + EPSV);
    const float alpha = __ldg(alpha_ptr);

    lsum = 0.f; lsq = 0.f;
    #pragma unroll
    for (int r = 0; r < TP; r++)
        #pragma unroll
        for (int c = 0; c < TP; c++) {
            float t = (acc[r][c] - m) * rs;
            t = (t >= 0.f) ? t : alpha * t;
            acc[r][c] = t;
            lsum += t;
            lsq  += t * t;
        }

    if (MODE == 1) {
        #pragma unroll
        for (int r = 0; r < TP; r++)
            #pragma unroll
            for (int c = 0; c < TP; c++)
                ob[(py0 + r) * H + (px0 + c)] = acc[r][c];
        return;
    }

    // MODE 0: second inorm + residual
    float m2, v2;
    blk_stats(lsum, lsq, s_red, tid, inv, m2, v2);
    float rs2 = rsqrtf(v2 + EPSV);
    const float* rb = resid + ((size_t)n * CIN + cout) * H * H;
    #pragma unroll
    for (int r = 0; r < TP; r++)
        #pragma unroll
        for (int c = 0; c < TP; c++) {
            int idx = (py0 + r) * H + (px0 + c);
            ob[idx] = (acc[r][c] - m2) * rs2 + rb[idx];
        }
}

// ---------------- fused: bilinear-8x upsample of skernel + softmax + 3x3 reflect apply --
// grid (16,16,4), block 256 = 16x16; one thread per (h,w), all 48 channels.
__global__ void __launch_bounds__(256)
apply_kernel_fused(const float* __restrict__ x, const float* __restrict__ sk,
                   float* __restrict__ out) {
    const int n = blockIdx.z;
    const int w = blockIdx.x * 16 + (threadIdx.x & 15);
    const int h = blockIdx.y * 16 + (threadIdx.x >> 4);

    // align-corners bilinear coords: src = o*31/255
    float fh = ((float)h * 31.0f) / 255.0f;
    int r0 = (int)floorf(fh);
    float fr = fh - (float)r0;
    int r1 = min(r0 + 1, 31);
    float fw = ((float)w * 31.0f) / 255.0f;
    int c0 = (int)floorf(fw);
    float fc = fw - (float)c0;
    int c1 = min(c0 + 1, 31);

    const float w00 = (1.f - fr) * (1.f - fc);
    const float w01 = (1.f - fr) * fc;
    const float w10 = fr * (1.f - fc);
    const float w11 = fr * fc;

    float kv[9];
    const float* skb = sk + (size_t)n * 9 * 1024;
    #pragma unroll
    for (int p = 0; p < 9; p++) {
        const float* s = skb + p * 1024;
        kv[p] = w00 * __ldg(&s[r0 * 32 + c0]) + w01 * __ldg(&s[r0 * 32 + c1])
              + w10 * __ldg(&s[r1 * 32 + c0]) + w11 * __ldg(&s[r1 * 32 + c1]);
    }
    // softmax over the 9 taps
    float mx = kv[0];
    #pragma unroll
    for (int p = 1; p < 9; p++) mx = fmaxf(mx, kv[p]);
    float sum = 0.f;
    #pragma unroll
    for (int p = 0; p < 9; p++) { kv[p] = expf(kv[p] - mx); sum += kv[p]; }
    float is = 1.0f / sum;
    #pragma unroll
    for (int p = 0; p < 9; p++) kv[p] *= is;

    // reflect-padded neighbor indices
    int rows[3], cols[3];
    rows[0] = (h == 0) ? 1 : h - 1;  rows[1] = h;  rows[2] = (h == 255) ? 254 : h + 1;
    cols[0] = (w == 0) ? 1 : w - 1;  cols[1] = w;  cols[2] = (w == 255) ? 254 : w + 1;

    const float* xb = x + (size_t)n * 48 * 65536;
    float* ob = out + (size_t)n * 48 * 65536 + h * 256 + w;

    for (int c = 0; c < 48; c++) {
        const float* xc = xb + (size_t)c * 65536;
        float s = 0.f;
        #pragma unroll
        for (int dy = 0; dy < 3; dy++) {
            const float* xr = xc + rows[dy] * 256;
            #pragma unroll
            for (int dx = 0; dx < 3; dx++)
                s = fmaf(kv[dy * 3 + dx], __ldg(&xr[cols[dx]]), s);
        }
        ob[(size_t)c * 65536] = s;
    }
}

// ---------------- host launcher ----------------
extern "C" void kernel_launch(void* const* d_in, const int* in_sizes, int n_in,
                              void* d_out, int out_size) {
    const float* x   = (const float*)d_in[0];
    const float* x_  = (const float*)d_in[1];
    const float* p1w = (const float*)d_in[2];
    const float* p1b = (const float*)d_in[3];
    const float* p1a = (const float*)d_in[4];
    const float* p2w = (const float*)d_in[5];
    const float* p2b = (const float*)d_in[6];
    const float* p2a = (const float*)d_in[7];
    const float* kw1 = (const float*)d_in[8];
    const float* kb1 = (const float*)d_in[9];
    const float* ka  = (const float*)d_in[10];
    const float* kw2 = (const float*)d_in[11];
    const float* kb2 = (const float*)d_in[12];
    float* out = (float*)d_out;

    float *ga, *gb, *gc, *gd, *gsk;
    cudaGetSymbolAddress((void**)&ga,  g_a);
    cudaGetSymbolAddress((void**)&gb,  g_b);
    cudaGetSymbolAddress((void**)&gc,  g_c);
    cudaGetSymbolAddress((void**)&gd,  g_d);
    cudaGetSymbolAddress((void**)&gsk, g_sk);

    // x1 = x_[:, :, ::4, ::4]
    down_kernel<<<(4*48*64*64 + 255) / 256, 256>>>(x_, ga);

    // 3 basic blocks @ 64x64  (a->b->a->b)
    const size_t WSTRIDE = (size_t)48 * 48 * 9;
    conv_block<64, 4, 0><<<dim3(48, 4), 256>>>(ga, ga, gb, p1w + 0 * WSTRIDE, p1b + 0, p1a + 0);
    conv_block<64, 4, 0><<<dim3(48, 4), 256>>>(gb, gb, ga, p1w + 1 * WSTRIDE, p1b + 48, p1a + 1);
    conv_block<64, 4, 0><<<dim3(48, 4), 256>>>(ga, ga, gb, p1w + 2 * WSTRIDE, p1b + 96, p1a + 2);

    // maxpool -> 32x32
    pool_kernel<<<(4*48*32*32 + 255) / 256, 256>>>(gb, gc);

    // 3 basic blocks @ 32x32 (c->d->c->d)
    conv_block<32, 2, 0><<<dim3(48, 4), 256>>>(gc, gc, gd, p2w + 0 * WSTRIDE, p2b + 0, p2a + 0);
    conv_block<32, 2, 0><<<dim3(48, 4), 256>>>(gd, gd, gc, p2w + 1 * WSTRIDE, p2b + 48, p2a + 1);
    conv_block<32, 2, 0><<<dim3(48, 4), 256>>>(gc, gc, gd, p2w + 2 * WSTRIDE, p2b + 96, p2a + 2);

    // y = prelu(inorm(conv(x1, kw1)+kb1))    d -> c
    conv_block<32, 2, 1><<<dim3(48, 4), 256>>>(gd, nullptr, gc, kw1, kb1, ka);

    // skernel = conv(y, kw2)+kb2             c -> sk  (9 out channels)
    conv_block<32, 2, 2><<<dim3(9, 4), 256>>>(gc, nullptr, gsk, kw2, kb2, ka);

    // fused upsample + softmax + adaptive 3x3 apply on full-res x
    apply_kernel_fused<<<dim3(16, 16, 4), 256>>>(x, gsk, out);
}

// round 3
// speedup vs baseline: 1.6391x; 1.6391x over previous
#include <cuda_runtime.h>
#include <math.h>

#define EPSV 1e-5f

// ---------------- scratch buffers (no allocation allowed) ----------------
__device__ float g_a[4*48*64*64];
__device__ float g_b[4*48*64*64];
__device__ float g_c[4*48*32*32];
__device__ float g_d[4*48*32*32];
__device__ float g_sk[4*9*32*32];

// ---------------- x1 = x_[:, :, ::4, ::4] ----------------
__global__ void down_kernel(const float* __restrict__ xs, float* __restrict__ out) {
    int i = blockIdx.x * blockDim.x + threadIdx.x;
    if (i >= 4*48*64*64) return;
    int w  = i & 63;
    int t  = i >> 6;
    int h  = t & 63;
    int nc = t >> 6;
    out[i] = xs[((size_t)nc * 256 + (size_t)h * 4) * 256 + (size_t)w * 4];
}

// ---------------- 2x2 maxpool ----------------
__global__ void pool_kernel(const float* __restrict__ in, float* __restrict__ out) {
    int i = blockIdx.x * blockDim.x + threadIdx.x;
    if (i >= 4*48*32*32) return;
    int w  = i & 31;
    int t  = i >> 5;
    int h  = t & 31;
    int nc = t >> 5;
    const float* p = in + ((size_t)nc * 64 + (size_t)h * 2) * 64 + (size_t)w * 2;
    out[i] = fmaxf(fmaxf(p[0], p[1]), fmaxf(p[64], p[65]));
}

// ---------------- block-wide (sum, sumsq) reduction over 256 threads ----------------
__device__ __forceinline__ void blk_stats(float lsum, float lsq, float* sred, int tid,
                                          float inv, float& mean, float& var) {
    __syncthreads();
    #pragma unroll
    for (int o = 16; o; o >>= 1) {
        lsum += __shfl_xor_sync(0xffffffffu, lsum, o);
        lsq  += __shfl_xor_sync(0xffffffffu, lsq,  o);
    }
    if ((tid & 31) == 0) { sred[tid >> 5] = lsum; sred[8 + (tid >> 5)] = lsq; }
    __syncthreads();
    if (tid == 0) {
        float a = 0.f, b = 0.f;
        #pragma unroll
        for (int i = 0; i < 8; i++) { a += sred[i]; b += sred[8 + i]; }
        sred[16] = a; sred[17] = b;
    }
    __syncthreads();
    mean = sred[16] * inv;
    var  = sred[17] * inv - mean * mean;
}

// ---------------- tiled conv3x3 (48 -> COUT), conv + bias only ----------------
// Tile: 32 wide x 16 high, 256 threads as 16x16, 2 px per thread (x-dir).
// KO output channels per CTA. Double-buffered input tile in smem.
// Weights staged transposed: s_w[(ci*9+k)*KO + ko] -> LDS.128 when KO==4.
template<int H, int COUT, int KO>
__global__ void __launch_bounds__(256)
conv_tiled(const float* __restrict__ in, float* __restrict__ out,
           const float* __restrict__ W, const float* __restrict__ B) {
    constexpr int TW = 32, TH = 16;
    constexpr int TILES_X = H / TW;
    constexpr int SROW = TW + 3;                    // 35: odd stride, conflict-free
    constexpr int TEL = (TH + 2) * (TW + 2);        // 18*34 = 612

    __shared__ float s_t[2][(TH + 2) * SROW];
    __shared__ float s_w[48 * 9 * KO];

    const int tid  = threadIdx.x;
    const int tx   = tid & 15, ty = tid >> 4;
    const int tile = blockIdx.x;
    const int g    = blockIdx.y;
    const int n    = blockIdx.z;
    const int tx0  = (tile % TILES_X) * TW;
    const int ty0  = (tile / TILES_X) * TH;

    // stage weights transposed
    for (int i = tid; i < 48 * 9 * KO; i += 256) {
        int ko = i % KO;
        int rest = i / KO;
        int k = rest % 9, ci = rest / 9;
        s_w[i] = W[(((size_t)(g * KO + ko)) * 48 + ci) * 9 + k];
    }

    const float* inb = in + (size_t)n * 48 * H * H;

    auto load_tile = [&](int ci, int buf) {
        const float* ch = inb + (size_t)ci * H * H;
        for (int e = tid; e < TEL; e += 256) {
            int r = e / (TW + 2), c = e - r * (TW + 2);
            int gr = ty0 + r - 1, gc = tx0 + c - 1;
            float v = 0.f;
            if ((unsigned)gr < (unsigned)H && (unsigned)gc < (unsigned)H)
                v = ch[gr * H + gc];
            s_t[buf][r * SROW + c] = v;
        }
    };

    float acc[KO][2];
    #pragma unroll
    for (int ko = 0; ko < KO; ko++) { acc[ko][0] = 0.f; acc[ko][1] = 0.f; }

    load_tile(0, 0);

    for (int ci = 0; ci < 48; ci++) {
        __syncthreads();                  // buf[ci&1] ready; prev compute done
        if (ci + 1 < 48) load_tile(ci + 1, (ci + 1) & 1);
        const float* buf = s_t[ci & 1];

        float win[3][4];
        #pragma unroll
        for (int r = 0; r < 3; r++)
            #pragma unroll
            for (int c = 0; c < 4; c++)
                win[r][c] = buf[(ty + r) * SROW + tx * 2 + c];

        #pragma unroll
        for (int k = 0; k < 9; k++) {
            const int dy = k / 3, dx = k % 3;
            float wv[KO];
            if (KO == 4) {
                float4 w4 = *(const float4*)&s_w[(ci * 9 + k) * 4];
                wv[0] = w4.x; wv[1] = w4.y; wv[2] = w4.z; wv[3] = w4.w;
            } else {
                #pragma unroll
                for (int ko = 0; ko < KO; ko++) wv[ko] = s_w[(ci * 9 + k) * KO + ko];
            }
            #pragma unroll
            for (int ko = 0; ko < KO; ko++) {
                acc[ko][0] = fmaf(win[dy][dx    ], wv[ko], acc[ko][0]);
                acc[ko][1] = fmaf(win[dy][dx + 1], wv[ko], acc[ko][1]);
            }
        }
    }

    const int gy  = ty0 + ty;
    const int gxb = tx0 + tx * 2;
    #pragma unroll
    for (int ko = 0; ko < KO; ko++) {
        int co = g * KO + ko;
        float b = B[co];
        float2 v = make_float2(acc[ko][0] + b, acc[ko][1] + b);
        *(float2*)&out[(((size_t)n * COUT + co) * H + gy) * H + gxb] = v;
    }
}

// ---------------- instance-norm tail kernels ----------------
// FULL=true : inorm, prelu, inorm, + residual  (basic block tail)
// FULL=false: inorm, prelu                     (head)
// grid (48, 4), block 256; each thread holds H*H/256 px in registers.
template<int H, bool FULL>
__global__ void __launch_bounds__(256)
norm_kernel(const float* __restrict__ y, const float* __restrict__ resid,
            float* __restrict__ out, const float* __restrict__ alpha_ptr) {
    constexpr int PX = H * H / 256;
    __shared__ float sred[18];
    const int c = blockIdx.x, n = blockIdx.y, tid = threadIdx.x;
    const size_t base = ((size_t)n * 48 + c) * H * H;
    const float inv = 1.0f / (float)(H * H);

    float v[PX];
    float lsum = 0.f, lsq = 0.f;
    #pragma unroll
    for (int i = 0; i < PX; i++) {
        v[i] = y[base + tid + i * 256];
        lsum += v[i]; lsq += v[i] * v[i];
    }
    float m, va;
    blk_stats(lsum, lsq, sred, tid, inv, m, va);
    float rs = rsqrtf(va + EPSV);
    const float alpha = __ldg(alpha_ptr);

    lsum = 0.f; lsq = 0.f;
    #pragma unroll
    for (int i = 0; i < PX; i++) {
        float t = (v[i] - m) * rs;
        t = (t >= 0.f) ? t : alpha * t;
        v[i] = t;
        lsum += t; lsq += t * t;
    }

    if (!FULL) {
        #pragma unroll
        for (int i = 0; i < PX; i++) out[base + tid + i * 256] = v[i];
        return;
    }

    float m2, v2;
    blk_stats(lsum, lsq, sred, tid, inv, m2, v2);
    float rs2 = rsqrtf(v2 + EPSV);
    #pragma unroll
    for (int i = 0; i < PX; i++) {
        size_t idx = base + tid + i * 256;
        out[idx] = (v[i] - m2) * rs2 + resid[idx];
    }
}

// ---------------- fused upsample + softmax + 3x3 reflect apply ----------------
// grid (16,16,4), block 256 = 16x16 px tile. x staged in double-buffered smem.
__global__ void __launch_bounds__(256)
apply_kernel_fused(const float* __restrict__ x, const float* __restrict__ sk,
                   float* __restrict__ out) {
    __shared__ float s_t[2][18 * 19];
    const int n   = blockIdx.z;
    const int tid = threadIdx.x;
    const int txx = tid & 15, tyy = tid >> 4;
    const int w0 = blockIdx.x * 16, h0 = blockIdx.y * 16;
    const int w = w0 + txx, h = h0 + tyy;

    // align-corners bilinear coords: src = o*31/255
    float fh = ((float)h * 31.0f) / 255.0f;
    int r0 = (int)floorf(fh);
    float fr = fh - (float)r0;
    int r1 = min(r0 + 1, 31);
    float fw = ((float)w * 31.0f) / 255.0f;
    int c0 = (int)floorf(fw);
    float fc = fw - (float)c0;
    int c1 = min(c0 + 1, 31);

    const float w00 = (1.f - fr) * (1.f - fc);
    const float w01 = (1.f - fr) * fc;
    const float w10 = fr * (1.f - fc);
    const float w11 = fr * fc;

    float kv[9];
    const float* skb = sk + (size_t)n * 9 * 1024;
    #pragma unroll
    for (int p = 0; p < 9; p++) {
        const float* s = skb + p * 1024;
        kv[p] = w00 * __ldg(&s[r0 * 32 + c0]) + w01 * __ldg(&s[r0 * 32 + c1])
              + w10 * __ldg(&s[r1 * 32 + c0]) + w11 * __ldg(&s[r1 * 32 + c1]);
    }
    float mx = kv[0];
    #pragma unroll
    for (int p = 1; p < 9; p++) mx = fmaxf(mx, kv[p]);
    float sum = 0.f;
    #pragma unroll
    for (int p = 0; p < 9; p++) { kv[p] = expf(kv[p] - mx); sum += kv[p]; }
    float is = 1.0f / sum;
    #pragma unroll
    for (int p = 0; p < 9; p++) kv[p] *= is;

    const float* xb = x + (size_t)n * 48 * 65536;
    float* ob = out + (size_t)n * 48 * 65536 + (size_t)h * 256 + w;

    auto load_tile = [&](int c, int buf) {
        const float* xc = xb + (size_t)c * 65536;
        for (int e = tid; e < 324; e += 256) {
            int r = e / 18, cc = e - r * 18;
            int gr = h0 + r - 1; gr = gr < 0 ? -gr : (gr > 255 ? 510 - gr : gr);
            int gc = w0 + cc - 1; gc = gc < 0 ? -gc : (gc > 255 ? 510 - gc : gc);
            s_t[buf][r * 19 + cc] = xc[gr * 256 + gc];
        }
    };

    load_tile(0, 0);
    for (int c = 0; c < 48; c++) {
        __syncthreads();
        if (c + 1 < 48) load_tile(c + 1, (c + 1) & 1);
        const float* buf = s_t[c & 1];
        float s = 0.f;
        #pragma unroll
        for (int dy = 0; dy < 3; dy++)
            #pragma unroll
            for (int dx = 0; dx < 3; dx++)
                s = fmaf(kv[dy * 3 + dx], buf[(tyy + dy) * 19 + txx + dx], s);
        ob[(size_t)c * 65536] = s;
    }
}

// ---------------- host launcher ----------------
extern "C" void kernel_launch(void* const* d_in, const int* in_sizes, int n_in,
                              void* d_out, int out_size) {
    const float* x   = (const float*)d_in[0];
    const float* x_  = (const float*)d_in[1];
    const float* p1w = (const float*)d_in[2];
    const float* p1b = (const float*)d_in[3];
    const float* p1a = (const float*)d_in[4];
    const float* p2w = (const float*)d_in[5];
    const float* p2b = (const float*)d_in[6];
    const float* p2a = (const float*)d_in[7];
    const float* kw1 = (const float*)d_in[8];
    const float* kb1 = (const float*)d_in[9];
    const float* ka  = (const float*)d_in[10];
    const float* kw2 = (const float*)d_in[11];
    const float* kb2 = (const float*)d_in[12];
    float* out = (float*)d_out;

    float *ga, *gb, *gc, *gd, *gsk;
    cudaGetSymbolAddress((void**)&ga,  g_a);
    cudaGetSymbolAddress((void**)&gb,  g_b);
    cudaGetSymbolAddress((void**)&gc,  g_c);
    cudaGetSymbolAddress((void**)&gd,  g_d);
    cudaGetSymbolAddress((void**)&gsk, g_sk);

    const size_t WS = (size_t)48 * 48 * 9;
    const dim3 g64(8, 12, 4);    // (64/32)*(64/16) tiles, 48/4 groups, n
    const dim3 g32(2, 12, 4);
    const dim3 gnorm(48, 4);

    // x1 = x_[:, :, ::4, ::4]
    down_kernel<<<(4*48*64*64 + 255) / 256, 256>>>(x_, ga);

    // 3 basic blocks @ 64x64
    conv_tiled<64, 48, 4><<<g64, 256>>>(ga, gb, p1w + 0 * WS, p1b + 0);
    norm_kernel<64, true><<<gnorm, 256>>>(gb, ga, gb, p1a + 0);
    conv_tiled<64, 48, 4><<<g64, 256>>>(gb, ga, p1w + 1 * WS, p1b + 48);
    norm_kernel<64, true><<<gnorm, 256>>>(ga, gb, ga, p1a + 1);
    conv_tiled<64, 48, 4><<<g64, 256>>>(ga, gb, p1w + 2 * WS, p1b + 96);
    norm_kernel<64, true><<<gnorm, 256>>>(gb, ga, gb, p1a + 2);

    // maxpool -> 32x32
    pool_kernel<<<(4*48*32*32 + 255) / 256, 256>>>(gb, gc);

    // 3 basic blocks @ 32x32
    conv_tiled<32, 48, 4><<<g32, 256>>>(gc, gd, p2w + 0 * WS, p2b + 0);
    norm_kernel<32, true><<<gnorm, 256>>>(gd, gc, gd, p2a + 0);
    conv_tiled<32, 48, 4><<<g32, 256>>>(gd, gc, p2w + 1 * WS, p2b + 48);
    norm_kernel<32, true><<<gnorm, 256>>>(gc, gd, gc, p2a + 1);
    conv_tiled<32, 48, 4><<<g32, 256>>>(gc, gd, p2w + 2 * WS, p2b + 96);
    norm_kernel<32, true><<<gnorm, 256>>>(gd, gc, gd, p2a + 2);

    // head: conv + inorm + prelu
    conv_tiled<32, 48, 4><<<g32, 256>>>(gd, gc, kw1, kb1);
    norm_kernel<32, false><<<gnorm, 256>>>(gc, nullptr, gc, ka);

    // skernel = conv(y) + bias  (9 out channels)
    conv_tiled<32, 9, 3><<<dim3(2, 3, 4), 256>>>(gc, gsk, kw2, kb2);

    // fused upsample + softmax + adaptive 3x3 apply
    apply_kernel_fused<<<dim3(16, 16, 4), 256>>>(x, gsk, out);
}

// round 4
// speedup vs baseline: 3.1698x; 1.9339x over previous
#include <cuda_runtime.h>
#include <cstdint>
#include <math.h>

#define EPSV 1e-5f

// ---------------- scratch (no allocation allowed) ----------------
__device__ float g_a[4*48*64*64];
__device__ float g_b[4*48*64*64];
__device__ float g_c[4*48*32*32];
__device__ float g_d[4*48*32*32];
__device__ float g_p[2*4*48*32*32];   // split-K partials for 32^2 convs
__device__ float g_skp[2*4*9*32*32];  // split-K partials for skernel conv

// ---------------- cp.async helpers ----------------
__device__ __forceinline__ uint32_t s2u(const void* p) {
    return (uint32_t)__cvta_generic_to_shared(p);
}
__device__ __forceinline__ void cp4(uint32_t dst, const float* src, int src_sz) {
    asm volatile("cp.async.ca.shared.global [%0], [%1], 4, %2;\n"
                 :: "r"(dst), "l"(src), "r"(src_sz));
}
#define CP_COMMIT() asm volatile("cp.async.commit_group;\n" ::: "memory")
#define CP_WAIT1()  asm volatile("cp.async.wait_group 1;\n" ::: "memory")

// ---------------- x1 = x_[:, :, ::4, ::4] ----------------
__global__ void down_kernel(const float* __restrict__ xs, float* __restrict__ out) {
    int i = blockIdx.x * blockDim.x + threadIdx.x;
    if (i >= 4*48*64*64) return;
    int w  = i & 63;
    int t  = i >> 6;
    int h  = t & 63;
    int nc = t >> 6;
    out[i] = xs[((size_t)nc * 256 + (size_t)h * 4) * 256 + (size_t)w * 4];
}

// ---------------- 2x2 maxpool ----------------
__global__ void pool_kernel(const float* __restrict__ in, float* __restrict__ out) {
    int i = blockIdx.x * blockDim.x + threadIdx.x;
    if (i >= 4*48*32*32) return;
    int w  = i & 31;
    int t  = i >> 5;
    int h  = t & 31;
    int nc = t >> 5;
    const float* p = in + ((size_t)nc * 64 + (size_t)h * 2) * 64 + (size_t)w * 2;
    out[i] = fmaxf(fmaxf(p[0], p[1]), fmaxf(p[64], p[65]));
}

// ---------------- block-wide (sum, sumsq) reduction ----------------
__device__ __forceinline__ void blk_stats(float lsum, float lsq, float* sred, int tid,
                                          float inv, float& mean, float& var) {
    __syncthreads();
    #pragma unroll
    for (int o = 16; o; o >>= 1) {
        lsum += __shfl_xor_sync(0xffffffffu, lsum, o);
        lsq  += __shfl_xor_sync(0xffffffffu, lsq,  o);
    }
    if ((tid & 31) == 0) { sred[tid >> 5] = lsum; sred[8 + (tid >> 5)] = lsq; }
    __syncthreads();
    if (tid == 0) {
        float a = 0.f, b = 0.f;
        #pragma unroll
        for (int i = 0; i < 8; i++) { a += sred[i]; b += sred[8 + i]; }
        sred[16] = a; sred[17] = b;
    }
    __syncthreads();
    mean = sred[16] * inv;
    var  = sred[17] * inv - mean * mean;
}

// ---------------- conv3x3 (48 -> COUT), cp.async pipelined, no bias ----------------
// Tile 32x16, 256 threads as 16x16, 2 px/thread (x). KO couts per CTA.
// SPLIT-way split over input channels: CTA sums 48/SPLIT channels, writes partial
// buffer sp (bias + partial-sum handled by the consumer kernel).
template<int H, int COUT, int KO, int SPLIT>
__global__ void __launch_bounds__(256)
conv_fast(const float* __restrict__ in, float* __restrict__ out,
          const float* __restrict__ W) {
    constexpr int TW = 32, TH = 16, SROW = 36;
    constexpr int TILES_X = H / TW;
    constexpr int CN   = 48 / SPLIT;
    constexpr int TEL  = (TH + 2) * (TW + 2);      // 612
    constexpr int NLD  = (TEL + 255) / 256;        // 3
    constexpr int BUFSZ = (TH + 2) * SROW;         // 648

    __shared__ float s_t[3][BUFSZ];
    __shared__ float s_w[CN * 9 * KO];

    const int tid = threadIdx.x;
    const int tx  = tid & 15, ty = tid >> 4;
    const int tile = blockIdx.x, g = blockIdx.y;
    const int n  = blockIdx.z / SPLIT, sp = blockIdx.z % SPLIT;
    const int ci0 = sp * CN;
    const int tx0 = (tile % TILES_X) * TW;
    const int ty0 = (tile / TILES_X) * TH;

    // stage weights transposed: s_w[(ci*9+k)*KO + ko]
    for (int i = tid; i < CN * 9 * KO; i += 256) {
        int ko = i % KO;
        int rest = i / KO;
        int k = rest % 9, ci = rest / 9;
        s_w[i] = W[(((size_t)(g * KO + ko)) * 48 + ci0 + ci) * 9 + k];
    }

    // precompute tile-load slots (reused every channel)
    const float* inb = in + ((size_t)n * 48 + ci0) * H * H;
    int goff[NLD], soff[NLD], vsz[NLD]; bool act[NLD];
    #pragma unroll
    for (int j = 0; j < NLD; j++) {
        int e = tid + j * 256;
        int r = e / (TW + 2), c = e - r * (TW + 2);
        int gr = ty0 + r - 1, gc = tx0 + c - 1;
        act[j]  = (e < TEL);
        bool ok = act[j] && (unsigned)gr < (unsigned)H && (unsigned)gc < (unsigned)H;
        vsz[j]  = ok ? 4 : 0;                     // 0 -> zfill (SAME padding)
        goff[j] = ok ? gr * H + gc : 0;
        soff[j] = act[j] ? r * SROW + c : 0;
    }
    uint32_t sb0 = s2u(s_t[0]), sb1 = s2u(s_t[1]), sb2 = s2u(s_t[2]);
    uint32_t sb[3] = { sb0, sb1, sb2 };

    auto ldtile = [&](int ci, int b) {
        const float* ch = inb + (size_t)ci * H * H;
        #pragma unroll
        for (int j = 0; j < NLD; j++)
            if (act[j]) cp4(sb[b] + (uint32_t)soff[j] * 4, ch + goff[j], vsz[j]);
    };

    float acc[KO][2];
    #pragma unroll
    for (int ko = 0; ko < KO; ko++) { acc[ko][0] = 0.f; acc[ko][1] = 0.f; }

    ldtile(0, 0);
    CP_COMMIT();
    __syncthreads();      // s_w visible

    for (int ci = 0; ci < CN; ci++) {
        if (ci + 1 < CN) ldtile(ci + 1, (ci + 1) % 3);
        CP_COMMIT();
        CP_WAIT1();       // tile ci landed
        __syncthreads();

        const float* buf = s_t[ci % 3];
        float win[3][4];
        #pragma unroll
        for (int r = 0; r < 3; r++) {
            float2 a = *(const float2*)&buf[(ty + r) * SROW + tx * 2];
            float2 b = *(const float2*)&buf[(ty + r) * SROW + tx * 2 + 2];
            win[r][0] = a.x; win[r][1] = a.y; win[r][2] = b.x; win[r][3] = b.y;
        }

        #pragma unroll
        for (int k = 0; k < 9; k++) {
            const int dy = k / 3, dx = k % 3;
            float wv[KO];
            if (KO == 4) {
                float4 w4 = *(const float4*)&s_w[(ci * 9 + k) * 4];
                wv[0] = w4.x; wv[1] = w4.y; wv[2] = w4.z; wv[3] = w4.w;
            } else {
                #pragma unroll
                for (int ko = 0; ko < KO; ko++) wv[ko] = s_w[(ci * 9 + k) * KO + ko];
            }
            #pragma unroll
            for (int ko = 0; ko < KO; ko++) {
                acc[ko][0] = fmaf(win[dy][dx    ], wv[ko], acc[ko][0]);
                acc[ko][1] = fmaf(win[dy][dx + 1], wv[ko], acc[ko][1]);
            }
        }
    }

    const int gy  = ty0 + ty;
    const int gxb = tx0 + tx * 2;
    float* ob = out + (size_t)sp * 4 * COUT * H * H;
    #pragma unroll
    for (int ko = 0; ko < KO; ko++) {
        int co = g * KO + ko;
        *(float2*)&ob[(((size_t)n * COUT + co) * H + gy) * H + gxb] =
            make_float2(acc[ko][0], acc[ko][1]);
    }
}

// ---------------- instance-norm tail (adds bias, merges split-K partials) -------
// FULL: inorm, prelu, inorm, +residual.  !FULL: inorm, prelu.
template<int H, bool FULL, bool TWO>
__global__ void __launch_bounds__(256)
norm_kernel(const float* __restrict__ y0, const float* __restrict__ y1,
            const float* __restrict__ B, const float* __restrict__ resid,
            float* __restrict__ out, const float* __restrict__ alpha_ptr) {
    constexpr int PX = H * H / 256;
    __shared__ float sred[18];
    const int c = blockIdx.x, n = blockIdx.y, tid = threadIdx.x;
    const size_t base = ((size_t)n * 48 + c) * H * H;
    const float inv = 1.0f / (float)(H * H);
    const float b = B[c];

    float v[PX];
    float lsum = 0.f, lsq = 0.f;
    #pragma unroll
    for (int i = 0; i < PX; i++) {
        size_t idx = base + tid + i * 256;
        float t = y0[idx] + b;
        if (TWO) t += y1[idx];
        v[i] = t;
        lsum += t; lsq += t * t;
    }
    float m, va;
    blk_stats(lsum, lsq, sred, tid, inv, m, va);
    float rs = rsqrtf(va + EPSV);
    const float alpha = __ldg(alpha_ptr);

    lsum = 0.f; lsq = 0.f;
    #pragma unroll
    for (int i = 0; i < PX; i++) {
        float t = (v[i] - m) * rs;
        t = (t >= 0.f) ? t : alpha * t;
        v[i] = t;
        lsum += t; lsq += t * t;
    }

    if (!FULL) {
        #pragma unroll
        for (int i = 0; i < PX; i++) out[base + tid + i * 256] = v[i];
        return;
    }

    float m2, v2;
    blk_stats(lsum, lsq, sred, tid, inv, m2, v2);
    float rs2 = rsqrtf(v2 + EPSV);
    #pragma unroll
    for (int i = 0; i < PX; i++) {
        size_t idx = base + tid + i * 256;
        out[idx] = (v[i] - m2) * rs2 + resid[idx];
    }
}

// ---------------- fused: bilinear-8x upsample + softmax + 3x3 reflect apply ----
// skernel comes as two split-K partials + bias (linear ops commute with interp).
__global__ void __launch_bounds__(256)
apply_fused(const float* __restrict__ x, const float* __restrict__ sk,
            const float* __restrict__ kb2, float* __restrict__ out) {
    constexpr int SROW = 20, BUFSZ = 18 * SROW;
    __shared__ float s_t[3][BUFSZ];

    const int n   = blockIdx.z;
    const int tid = threadIdx.x;
    const int txx = tid & 15, tyy = tid >> 4;
    const int w0 = blockIdx.x * 16, h0 = blockIdx.y * 16;
    const int w = w0 + txx, h = h0 + tyy;

    // bilinear (align corners): src = o*31/255
    float fh = ((float)h * 31.0f) / 255.0f;
    int r0 = (int)floorf(fh);
    float fr = fh - (float)r0;
    int r1 = min(r0 + 1, 31);
    float fw = ((float)w * 31.0f) / 255.0f;
    int c0 = (int)floorf(fw);
    float fc = fw - (float)c0;
    int c1 = min(c0 + 1, 31);
    const float w00 = (1.f - fr) * (1.f - fc);
    const float w01 = (1.f - fr) * fc;
    const float w10 = fr * (1.f - fc);
    const float w11 = fr * fc;

    float kv[9];
    const float* skb0 = sk + (size_t)n * 9 * 1024;
    const float* skb1 = skb0 + (size_t)4 * 9 * 1024;
    #pragma unroll
    for (int p = 0; p < 9; p++) {
        const float* s0 = skb0 + p * 1024;
        const float* s1 = skb1 + p * 1024;
        float a = w00 * (__ldg(&s0[r0*32+c0]) + __ldg(&s1[r0*32+c0]))
                + w01 * (__ldg(&s0[r0*32+c1]) + __ldg(&s1[r0*32+c1]))
                + w10 * (__ldg(&s0[r1*32+c0]) + __ldg(&s1[r1*32+c0]))
                + w11 * (__ldg(&s0[r1*32+c1]) + __ldg(&s1[r1*32+c1]));
        kv[p] = a + __ldg(&kb2[p]);
    }
    float mx = kv[0];
    #pragma unroll
    for (int p = 1; p < 9; p++) mx = fmaxf(mx, kv[p]);
    float sum = 0.f;
    #pragma unroll
    for (int p = 0; p < 9; p++) { kv[p] = __expf(kv[p] - mx); sum += kv[p]; }
    float is = 1.0f / sum;
    #pragma unroll
    for (int p = 0; p < 9; p++) kv[p] *= is;

    // precompute reflect-padded load slots (324 elems, <=2 per thread)
    int goff[2], soff[2]; bool act[2];
    #pragma unroll
    for (int j = 0; j < 2; j++) {
        int e = tid + j * 256;
        act[j] = (e < 324);
        int r = e / 18, cc = e - r * 18;
        int gr = h0 + r - 1; gr = gr < 0 ? -gr : (gr > 255 ? 510 - gr : gr);
        int gc = w0 + cc - 1; gc = gc < 0 ? -gc : (gc > 255 ? 510 - gc : gc);
        goff[j] = act[j] ? gr * 256 + gc : 0;
        soff[j] = act[j] ? r * SROW + cc : 0;
    }
    uint32_t sb[3] = { s2u(s_t[0]), s2u(s_t[1]), s2u(s_t[2]) };

    const float* xb = x + (size_t)n * 48 * 65536;
    float* ob = out + (size_t)n * 48 * 65536 + (size_t)h * 256 + w;

    auto ldch = [&](int c, int b) {
        const float* xc = xb + (size_t)c * 65536;
        #pragma unroll
        for (int j = 0; j < 2; j++)
            if (act[j]) cp4(sb[b] + (uint32_t)soff[j] * 4, xc + goff[j], 4);
    };

    ldch(0, 0);
    CP_COMMIT();

    for (int c = 0; c < 48; c++) {
        if (c + 1 < 48) ldch(c + 1, (c + 1) % 3);
        CP_COMMIT();
        CP_WAIT1();
        __syncthreads();
        const float* buf = s_t[c % 3];
        float s = 0.f;
        #pragma unroll
        for (int dy = 0; dy < 3; dy++)
            #pragma unroll
            for (int dx = 0; dx < 3; dx++)
                s = fmaf(kv[dy * 3 + dx], buf[(tyy + dy) * SROW + txx + dx], s);
        ob[(size_t)c * 65536] = s;
    }
}

// ---------------- host launcher ----------------
extern "C" void kernel_launch(void* const* d_in, const int* in_sizes, int n_in,
                              void* d_out, int out_size) {
    const float* x   = (const float*)d_in[0];
    const float* x_  = (const float*)d_in[1];
    const float* p1w = (const float*)d_in[2];
    const float* p1b = (const float*)d_in[3];
    const float* p1a = (const float*)d_in[4];
    const float* p2w = (const float*)d_in[5];
    const float* p2b = (const float*)d_in[6];
    const float* p2a = (const float*)d_in[7];
    const float* kw1 = (const float*)d_in[8];
    const float* kb1 = (const float*)d_in[9];
    const float* ka  = (const float*)d_in[10];
    const float* kw2 = (const float*)d_in[11];
    const float* kb2 = (const float*)d_in[12];
    float* out = (float*)d_out;

    float *ga, *gb, *gc, *gd, *gp, *gskp;
    cudaGetSymbolAddress((void**)&ga,   g_a);
    cudaGetSymbolAddress((void**)&gb,   g_b);
    cudaGetSymbolAddress((void**)&gc,   g_c);
    cudaGetSymbolAddress((void**)&gd,   g_d);
    cudaGetSymbolAddress((void**)&gp,   g_p);
    cudaGetSymbolAddress((void**)&gskp, g_skp);
    float* gp1 = gp + (size_t)4*48*32*32;

    const size_t WS = (size_t)48 * 48 * 9;
    const dim3 g64(8, 12, 4);     // 8 tiles, 12 cout-groups, n
    const dim3 g32(2, 12, 8);     // 2 tiles, 12 groups, n*split
    const dim3 gnorm(48, 4);

    // x1 = x_[:, :, ::4, ::4]
    down_kernel<<<(4*48*64*64 + 255) / 256, 256>>>(x_, ga);

    // 3 basic blocks @ 64x64 (no ci-split; bias folded into norm)
    conv_fast<64, 48, 4, 1><<<g64, 256>>>(ga, gb, p1w + 0 * WS);
    norm_kernel<64, true, false><<<gnorm, 256>>>(gb, nullptr, p1b + 0,  ga, gb, p1a + 0);
    conv_fast<64, 48, 4, 1><<<g64, 256>>>(gb, ga, p1w + 1 * WS);
    norm_kernel<64, true, false><<<gnorm, 256>>>(ga, nullptr, p1b + 48, gb, ga, p1a + 1);
    conv_fast<64, 48, 4, 1><<<g64, 256>>>(ga, gb, p1w + 2 * WS);
    norm_kernel<64, true, false><<<gnorm, 256>>>(gb, nullptr, p1b + 96, ga, gb, p1a + 2);

    // maxpool -> 32x32
    pool_kernel<<<(4*48*32*32 + 255) / 256, 256>>>(gb, gc);

    // 3 basic blocks @ 32x32 (2-way ci-split, merged in norm)
    conv_fast<32, 48, 4, 2><<<g32, 256>>>(gc, gp, p2w + 0 * WS);
    norm_kernel<32, true, true><<<gnorm, 256>>>(gp, gp1, p2b + 0,  gc, gd, p2a + 0);
    conv_fast<32, 48, 4, 2><<<g32, 256>>>(gd, gp, p2w + 1 * WS);
    norm_kernel<32, true, true><<<gnorm, 256>>>(gp, gp1, p2b + 48, gd, gc, p2a + 1);
    conv_fast<32, 48, 4, 2><<<g32, 256>>>(gc, gp, p2w + 2 * WS);
    norm_kernel<32, true, true><<<gnorm, 256>>>(gp, gp1, p2b + 96, gc, gd, p2a + 2);

    // head: conv + inorm + prelu
    conv_fast<32, 48, 4, 2><<<g32, 256>>>(gd, gp, kw1);
    norm_kernel<32, false, true><<<gnorm, 256>>>(gp, gp1, kb1, nullptr, gc, ka);

    // skernel conv (9 couts, split-K partials; bias added in apply)
    conv_fast<32, 9, 3, 2><<<dim3(2, 3, 8), 256>>>(gc, gskp, kw2);

    // fused upsample + softmax + adaptive 3x3 apply
    apply_fused<<<dim3(16, 16, 4), 256>>>(x, gskp, kb2, out);
}

// round 5
// speedup vs baseline: 3.7736x; 1.1905x over previous
#include <cuda_runtime.h>
#include <cstdint>
#include <math.h>

#define EPSV 1e-5f

// ---------------- scratch (no allocation allowed) ----------------
__device__ float g_a[4*48*64*64];
__device__ float g_b[4*48*64*64];
__device__ float g_p64[2*4*48*64*64];   // split-K partials, 64^2 convs
__device__ float g_c[4*48*32*32];
__device__ float g_d[4*48*32*32];
__device__ float g_p32[4*4*48*32*32];   // split-K partials, 32^2 convs
__device__ float g_skp[2*4*9*32*32];    // split-K partials, skernel conv

// ---------------- cp.async helpers ----------------
__device__ __forceinline__ uint32_t s2u(const void* p) {
    return (uint32_t)__cvta_generic_to_shared(p);
}
__device__ __forceinline__ void cp4(uint32_t dst, const float* src, int src_sz) {
    asm volatile("cp.async.ca.shared.global [%0], [%1], 4, %2;\n"
                 :: "r"(dst), "l"(src), "r"(src_sz));
}
#define CP_COMMIT() asm volatile("cp.async.commit_group;\n" ::: "memory")
#define CP_WAIT1()  asm volatile("cp.async.wait_group 1;\n" ::: "memory")

// ---------------- x1 = x_[:, :, ::4, ::4] ----------------
__global__ void down_kernel(const float* __restrict__ xs, float* __restrict__ out) {
    int i = blockIdx.x * blockDim.x + threadIdx.x;
    if (i >= 4*48*64*64) return;
    int w  = i & 63;
    int t  = i >> 6;
    int h  = t & 63;
    int nc = t >> 6;
    out[i] = xs[((size_t)nc * 256 + (size_t)h * 4) * 256 + (size_t)w * 4];
}

// ---------------- 2x2 maxpool ----------------
__global__ void pool_kernel(const float* __restrict__ in, float* __restrict__ out) {
    int i = blockIdx.x * blockDim.x + threadIdx.x;
    if (i >= 4*48*32*32) return;
    int w  = i & 31;
    int t  = i >> 5;
    int h  = t & 31;
    int nc = t >> 5;
    const float* p = in + ((size_t)nc * 64 + (size_t)h * 2) * 64 + (size_t)w * 2;
    out[i] = fmaxf(fmaxf(p[0], p[1]), fmaxf(p[64], p[65]));
}

// ---------------- block-wide (sum, sumsq) reduction ----------------
__device__ __forceinline__ void blk_stats(float lsum, float lsq, float* sred, int tid,
                                          float inv, float& mean, float& var) {
    __syncthreads();
    #pragma unroll
    for (int o = 16; o; o >>= 1) {
        lsum += __shfl_xor_sync(0xffffffffu, lsum, o);
        lsq  += __shfl_xor_sync(0xffffffffu, lsq,  o);
    }
    if ((tid & 31) == 0) { sred[tid >> 5] = lsum; sred[8 + (tid >> 5)] = lsq; }
    __syncthreads();
    if (tid == 0) {
        float a = 0.f, b = 0.f;
        #pragma unroll
        for (int i = 0; i < 8; i++) { a += sred[i]; b += sred[8 + i]; }
        sred[16] = a; sred[17] = b;
    }
    __syncthreads();
    mean = sred[16] * inv;
    var  = sred[17] * inv - mean * mean;
}

// ---------------- conv3x3 (48 -> COUT), cp.async pipelined, split-K, no bias ----
// Tile TW x 16, 256 threads as 16x16, PX px/thread in x. KO couts per CTA.
// Writes a partial sum for input-channel slice sp; consumer merges + adds bias.
template<int H, int TW, int PX, int COUT, int KO, int SPLIT>
__global__ void __launch_bounds__(256, 3)
conv_fast(const float* __restrict__ in, float* __restrict__ out,
          const float* __restrict__ W) {
    constexpr int TH = 16, SROW = TW + 4;
    constexpr int TILES_X = H / TW;
    constexpr int CN   = 48 / SPLIT;
    constexpr int TEL  = (TH + 2) * (TW + 2);
    constexpr int NLD  = (TEL + 255) / 256;
    constexpr int BUFSZ = (TH + 2) * SROW;

    __shared__ float s_t[3][BUFSZ];
    __shared__ float s_w[CN * 9 * KO];

    const int tid = threadIdx.x;
    const int tx  = tid & 15, ty = tid >> 4;
    const int tile = blockIdx.x, g = blockIdx.y;
    const int n  = blockIdx.z / SPLIT, sp = blockIdx.z % SPLIT;
    const int ci0 = sp * CN;
    const int tx0 = (tile % TILES_X) * TW;
    const int ty0 = (tile / TILES_X) * TH;

    // stage weights transposed: s_w[(ci*9+k)*KO + ko]
    for (int i = tid; i < CN * 9 * KO; i += 256) {
        int ko = i % KO;
        int rest = i / KO;
        int k = rest % 9, ci = rest / 9;
        s_w[i] = W[(((size_t)(g * KO + ko)) * 48 + ci0 + ci) * 9 + k];
    }

    // precompute tile-load slots (reused every channel)
    const float* inb = in + ((size_t)n * 48 + ci0) * H * H;
    int goff[NLD], soff[NLD], vsz[NLD]; bool act[NLD];
    #pragma unroll
    for (int j = 0; j < NLD; j++) {
        int e = tid + j * 256;
        int r = e / (TW + 2), c = e - r * (TW + 2);
        int gr = ty0 + r - 1, gc = tx0 + c - 1;
        act[j]  = (e < TEL);
        bool ok = act[j] && (unsigned)gr < (unsigned)H && (unsigned)gc < (unsigned)H;
        vsz[j]  = ok ? 4 : 0;                     // 0 -> zfill (SAME padding)
        goff[j] = ok ? gr * H + gc : 0;
        soff[j] = act[j] ? r * SROW + c : 0;
    }
    uint32_t sb[3] = { s2u(s_t[0]), s2u(s_t[1]), s2u(s_t[2]) };

    auto ldtile = [&](int ci, int b) {
        const float* ch = inb + (size_t)ci * H * H;
        #pragma unroll
        for (int j = 0; j < NLD; j++)
            if (act[j]) cp4(sb[b] + (uint32_t)soff[j] * 4, ch + goff[j], vsz[j]);
    };

    float acc[KO][PX];
    #pragma unroll
    for (int ko = 0; ko < KO; ko++)
        #pragma unroll
        for (int p = 0; p < PX; p++) acc[ko][p] = 0.f;

    ldtile(0, 0);
    CP_COMMIT();
    __syncthreads();      // s_w visible

    for (int ci = 0; ci < CN; ci++) {
        if (ci + 1 < CN) ldtile(ci + 1, (ci + 1) % 3);
        CP_COMMIT();
        CP_WAIT1();       // tile ci landed
        __syncthreads();

        const float* buf = s_t[ci % 3];
        float win[3][PX + 2];
        #pragma unroll
        for (int r = 0; r < 3; r++) {
            const float* rp = &buf[(ty + r) * SROW + tx * PX];
            if (PX == 4) {
                float4 a = *(const float4*)rp;
                float2 b = *(const float2*)(rp + 4);
                win[r][0] = a.x; win[r][1] = a.y; win[r][2] = a.z; win[r][3] = a.w;
                win[r][4] = b.x; win[r][5] = b.y;
            } else {
                float2 a = *(const float2*)rp;
                float2 b = *(const float2*)(rp + 2);
                win[r][0] = a.x; win[r][1] = a.y; win[r][2] = b.x; win[r][3] = b.y;
            }
        }

        #pragma unroll
        for (int k = 0; k < 9; k++) {
            const int dy = k / 3, dx = k % 3;
            float wv[KO];
            if (KO == 4) {
                float4 w4 = *(const float4*)&s_w[(ci * 9 + k) * 4];
                wv[0] = w4.x; wv[1] = w4.y; wv[2] = w4.z; wv[3] = w4.w;
            } else {
                #pragma unroll
                for (int ko = 0; ko < KO; ko++) wv[ko] = s_w[(ci * 9 + k) * KO + ko];
            }
            #pragma unroll
            for (int ko = 0; ko < KO; ko++)
                #pragma unroll
                for (int p = 0; p < PX; p++)
                    acc[ko][p] = fmaf(win[dy][dx + p], wv[ko], acc[ko][p]);
        }
    }

    const int gy  = ty0 + ty;
    const int gxb = tx0 + tx * PX;
    float* ob = out + (size_t)sp * 4 * COUT * H * H;
    #pragma unroll
    for (int ko = 0; ko < KO; ko++) {
        int co = g * KO + ko;
        float* dst = &ob[(((size_t)n * COUT + co) * H + gy) * H + gxb];
        if (PX == 4)
            *(float4*)dst = make_float4(acc[ko][0], acc[ko][1], acc[ko][2], acc[ko][3]);
        else
            *(float2*)dst = make_float2(acc[ko][0], acc[ko][1]);
    }
}

// ---------------- instance-norm tail (adds bias, merges NPART split-K partials) --
// FULL: inorm, prelu, inorm, +residual.  !FULL: inorm, prelu.
template<int H, bool FULL, int NPART>
__global__ void __launch_bounds__(256)
norm_kernel(const float* __restrict__ y, const float* __restrict__ B,
            const float* __restrict__ resid, float* __restrict__ out,
            const float* __restrict__ alpha_ptr) {
    constexpr int PX = H * H / 256;
    constexpr size_t PSTRIDE = (size_t)4 * 48 * H * H;
    __shared__ float sred[18];
    const int c = blockIdx.x, n = blockIdx.y, tid = threadIdx.x;
    const size_t base = ((size_t)n * 48 + c) * H * H;
    const float inv = 1.0f / (float)(H * H);
    const float b = B[c];

    float v[PX];
    float lsum = 0.f, lsq = 0.f;
    #pragma unroll
    for (int i = 0; i < PX; i++) {
        size_t idx = base + tid + i * 256;
        float t = b;
        #pragma unroll
        for (int p = 0; p < NPART; p++) t += y[p * PSTRIDE + idx];
        v[i] = t;
        lsum += t; lsq += t * t;
    }
    float m, va;
    blk_stats(lsum, lsq, sred, tid, inv, m, va);
    float rs = rsqrtf(va + EPSV);
    const float alpha = __ldg(alpha_ptr);

    lsum = 0.f; lsq = 0.f;
    #pragma unroll
    for (int i = 0; i < PX; i++) {
        float t = (v[i] - m) * rs;
        t = (t >= 0.f) ? t : alpha * t;
        v[i] = t;
        lsum += t; lsq += t * t;
    }

    if (!FULL) {
        #pragma unroll
        for (int i = 0; i < PX; i++) out[base + tid + i * 256] = v[i];
        return;
    }

    float m2, v2;
    blk_stats(lsum, lsq, sred, tid, inv, m2, v2);
    float rs2 = rsqrtf(v2 + EPSV);
    #pragma unroll
    for (int i = 0; i < PX; i++) {
        size_t idx = base + tid + i * 256;
        out[idx] = (v[i] - m2) * rs2 + resid[idx];
    }
}

// ---------------- fused: bilinear-8x upsample + softmax + 3x3 reflect apply ----
// skernel comes as two split-K partials + bias (linear ops commute with interp).
__global__ void __launch_bounds__(256)
apply_fused(const float* __restrict__ x, const float* __restrict__ sk,
            const float* __restrict__ kb2, float* __restrict__ out) {
    constexpr int SROW = 20, BUFSZ = 18 * SROW;
    __shared__ float s_t[3][BUFSZ];

    const int n   = blockIdx.z;
    const int tid = threadIdx.x;
    const int txx = tid & 15, tyy = tid >> 4;
    const int w0 = blockIdx.x * 16, h0 = blockIdx.y * 16;
    const int w = w0 + txx, h = h0 + tyy;

    // bilinear (align corners): src = o*31/255
    float fh = ((float)h * 31.0f) / 255.0f;
    int r0 = (int)floorf(fh);
    float fr = fh - (float)r0;
    int r1 = min(r0 + 1, 31);
    float fw = ((float)w * 31.0f) / 255.0f;
    int c0 = (int)floorf(fw);
    float fc = fw - (float)c0;
    int c1 = min(c0 + 1, 31);
    const float w00 = (1.f - fr) * (1.f - fc);
    const float w01 = (1.f - fr) * fc;
    const float w10 = fr * (1.f - fc);
    const float w11 = fr * fc;

    float kv[9];
    const float* skb0 = sk + (size_t)n * 9 * 1024;
    const float* skb1 = skb0 + (size_t)4 * 9 * 1024;
    #pragma unroll
    for (int p = 0; p < 9; p++) {
        const float* s0 = skb0 + p * 1024;
        const float* s1 = skb1 + p * 1024;
        float a = w00 * (__ldg(&s0[r0*32+c0]) + __ldg(&s1[r0*32+c0]))
                + w01 * (__ldg(&s0[r0*32+c1]) + __ldg(&s1[r0*32+c1]))
                + w10 * (__ldg(&s0[r1*32+c0]) + __ldg(&s1[r1*32+c0]))
                + w11 * (__ldg(&s0[r1*32+c1]) + __ldg(&s1[r1*32+c1]));
        kv[p] = a + __ldg(&kb2[p]);
    }
    float mx = kv[0];
    #pragma unroll
    for (int p = 1; p < 9; p++) mx = fmaxf(mx, kv[p]);
    float sum = 0.f;
    #pragma unroll
    for (int p = 0; p < 9; p++) { kv[p] = __expf(kv[p] - mx); sum += kv[p]; }
    float is = 1.0f / sum;
    #pragma unroll
    for (int p = 0; p < 9; p++) kv[p] *= is;

    // precompute reflect-padded load slots (324 elems, <=2 per thread)
    int goff[2], soff[2]; bool act[2];
    #pragma unroll
    for (int j = 0; j < 2; j++) {
        int e = tid + j * 256;
        act[j] = (e < 324);
        int r = e / 18, cc = e - r * 18;
        int gr = h0 + r - 1; gr = gr < 0 ? -gr : (gr > 255 ? 510 - gr : gr);
        int gc = w0 + cc - 1; gc = gc < 0 ? -gc : (gc > 255 ? 510 - gc : gc);
        goff[j] = act[j] ? gr * 256 + gc : 0;
        soff[j] = act[j] ? r * SROW + cc : 0;
    }
    uint32_t sb[3] = { s2u(s_t[0]), s2u(s_t[1]), s2u(s_t[2]) };

    const float* xb = x + (size_t)n * 48 * 65536;
    float* ob = out + (size_t)n * 48 * 65536 + (size_t)h * 256 + w;

    auto ldch = [&](int c, int b) {
        const float* xc = xb + (size_t)c * 65536;
        #pragma unroll
        for (int j = 0; j < 2; j++)
            if (act[j]) cp4(sb[b] + (uint32_t)soff[j] * 4, xc + goff[j], 4);
    };

    ldch(0, 0);
    CP_COMMIT();

    for (int c = 0; c < 48; c++) {
        if (c + 1 < 48) ldch(c + 1, (c + 1) % 3);
        CP_COMMIT();
        CP_WAIT1();
        __syncthreads();
        const float* buf = s_t[c % 3];
        float s = 0.f;
        #pragma unroll
        for (int dy = 0; dy < 3; dy++)
            #pragma unroll
            for (int dx = 0; dx < 3; dx++)
                s = fmaf(kv[dy * 3 + dx], buf[(tyy + dy) * SROW + txx + dx], s);
        ob[(size_t)c * 65536] = s;
    }
}

// ---------------- host launcher ----------------
extern "C" void kernel_launch(void* const* d_in, const int* in_sizes, int n_in,
                              void* d_out, int out_size) {
    const float* x   = (const float*)d_in[0];
    const float* x_  = (const float*)d_in[1];
    const float* p1w = (const float*)d_in[2];
    const float* p1b = (const float*)d_in[3];
    const float* p1a = (const float*)d_in[4];
    const float* p2w = (const float*)d_in[5];
    const float* p2b = (const float*)d_in[6];
    const float* p2a = (const float*)d_in[7];
    const float* kw1 = (const float*)d_in[8];
    const float* kb1 = (const float*)d_in[9];
    const float* ka  = (const float*)d_in[10];
    const float* kw2 = (const float*)d_in[11];
    const float* kb2 = (const float*)d_in[12];
    float* out = (float*)d_out;

    float *ga, *gb, *gc, *gd, *gp64, *gp32, *gskp;
    cudaGetSymbolAddress((void**)&ga,   g_a);
    cudaGetSymbolAddress((void**)&gb,   g_b);
    cudaGetSymbolAddress((void**)&gc,   g_c);
    cudaGetSymbolAddress((void**)&gd,   g_d);
    cudaGetSymbolAddress((void**)&gp64, g_p64);
    cudaGetSymbolAddress((void**)&gp32, g_p32);
    cudaGetSymbolAddress((void**)&gskp, g_skp);

    const size_t WS = (size_t)48 * 48 * 9;
    const dim3 g64(4, 12, 8);     // 4 tiles (64x16), 12 cout-groups, n*split2
    const dim3 g32(2, 12, 16);    // 2 tiles (32x16), 12 groups, n*split4
    const dim3 gnorm(48, 4);

    // x1 = x_[:, :, ::4, ::4]
    down_kernel<<<(4*48*64*64 + 255) / 256, 256>>>(x_, ga);

    // 3 basic blocks @ 64x64: conv (split2 partials) + norm (merge, bias, resid)
    conv_fast<64, 64, 4, 48, 4, 2><<<g64, 256>>>(ga, gp64, p1w + 0 * WS);
    norm_kernel<64, true, 2><<<gnorm, 256>>>(gp64, p1b + 0,  ga, gb, p1a + 0);
    conv_fast<64, 64, 4, 48, 4, 2><<<g64, 256>>>(gb, gp64, p1w + 1 * WS);
    norm_kernel<64, true, 2><<<gnorm, 256>>>(gp64, p1b + 48, gb, ga, p1a + 1);
    conv_fast<64, 64, 4, 48, 4, 2><<<g64, 256>>>(ga, gp64, p1w + 2 * WS);
    norm_kernel<64, true, 2><<<gnorm, 256>>>(gp64, p1b + 96, ga, gb, p1a + 2);

    // maxpool -> 32x32
    pool_kernel<<<(4*48*32*32 + 255) / 256, 256>>>(gb, gc);

    // 3 basic blocks @ 32x32 (4-way ci-split, merged in norm)
    conv_fast<32, 32, 2, 48, 4, 4><<<g32, 256>>>(gc, gp32, p2w + 0 * WS);
    norm_kernel<32, true, 4><<<gnorm, 256>>>(gp32, p2b + 0,  gc, gd, p2a + 0);
    conv_fast<32, 32, 2, 48, 4, 4><<<g32, 256>>>(gd, gp32, p2w + 1 * WS);
    norm_kernel<32, true, 4><<<gnorm, 256>>>(gp32, p2b + 48, gd, gc, p2a + 1);
    conv_fast<32, 32, 2, 48, 4, 4><<<g32, 256>>>(gc, gp32, p2w + 2 * WS);
    norm_kernel<32, true, 4><<<gnorm, 256>>>(gp32, p2b + 96, gc, gd, p2a + 2);

    // head: conv + inorm + prelu
    conv_fast<32, 32, 2, 48, 4, 4><<<g32, 256>>>(gd, gp32, kw1);
    norm_kernel<32, false, 4><<<gnorm, 256>>>(gp32, kb1, nullptr, gc, ka);

    // skernel conv (9 couts, split-K partials; bias added in apply)
    conv_fast<32, 32, 2, 9, 3, 2><<<dim3(2, 3, 8), 256>>>(gc, gskp, kw2);

    // fused upsample + softmax + adaptive 3x3 apply
    apply_fused<<<dim3(16, 16, 4), 256>>>(x, gskp, kb2, out);
}